// round 10
// baseline (speedup 1.0000x reference)
#include <cuda_runtime.h>
#include <cuda_bf16.h>
#include <math_constants.h>

#define NN 100000
#define EE 800000
#define GG 512
#define FF 64
#define OUTD 10

#define SCAN_CHUNK 1024
#define SCAN_BLOCKS ((NN + SCAN_CHUNK - 1) / SCAN_CHUNK)

// ---------------- scratch (device globals; no allocation allowed) -----------
__device__ int   d_cnt[NN];
__device__ float d_loop[NN];
__device__ int   d_off[NN + 1];
__device__ int   d_cur[NN];
__device__ int   d_bsum[SCAN_BLOCKS];
__device__ int   d_csr_src[EE];      // CSR: source node per slot
__device__ float d_w[EE];            // CSR: attention weight per slot (per layer)
__device__ int   d_pos[EE];          // original edge -> CSR slot
__device__ float d_xp[NN * FF];
__device__ float d_h[NN * FF];
__device__ float d_asrc[NN];
__device__ float d_adst[NN];
__device__ float d_cedge[2];

__device__ __forceinline__ float lrelu(float x) {
    return fmaxf(x, 0.2f * x);
}

// ---------------- zero + cedge (fused; single-warp, NO barrier) --------------
__global__ void zero_kernel(const float* __restrict__ We1, const float* __restrict__ ae1,
                            const float* __restrict__ We2, const float* __restrict__ ae2) {
    int i = blockIdx.x * blockDim.x + threadIdx.x;
    if (i < NN) { d_cnt[i] = 0; d_loop[i] = 0.f; }
    if (blockIdx.x == 0 && threadIdx.x < 32) {
        int t = threadIdx.x;
        float p1 = We1[t] * ae1[t] + We1[t + 32] * ae1[t + 32];
        float p2 = We2[t] * ae2[t] + We2[t + 32] * ae2[t + 32];
        #pragma unroll
        for (int o = 16; o > 0; o >>= 1) {
            p1 += __shfl_xor_sync(0xffffffff, p1, o);
            p2 += __shfl_xor_sync(0xffffffff, p2, o);
        }
        if (t == 0) { d_cedge[0] = p1; d_cedge[1] = p2; }
    }
}

// ---------------- CSR construction ------------------------------------------
__global__ void count_kernel(const int* __restrict__ ei, const float* __restrict__ ea) {
    int i = blockIdx.x * blockDim.x + threadIdx.x;
    if (i < EE) {
        int dd = ei[EE + i];
        atomicAdd(&d_cnt[dd], 1);
        atomicAdd(&d_loop[dd], ea[i]);
    }
}

// scan stage A: per-chunk sums
__global__ void scanA_kernel() {
    __shared__ int sh[256];
    int b = blockIdx.x, t = threadIdx.x;
    int s = 0;
    for (int i = t; i < SCAN_CHUNK; i += 256) {
        int idx = b * SCAN_CHUNK + i;
        if (idx < NN) s += d_cnt[idx];
    }
    sh[t] = s; __syncthreads();
    for (int o = 128; o > 0; o >>= 1) {
        if (t < o) sh[t] += sh[t + o];
        __syncthreads();
    }
    if (t == 0) d_bsum[b] = sh[0];
}

// scan stage B: parallel exclusive scan over the <=128 chunk sums
__global__ void scanB_kernel() {
    __shared__ int sh[128];
    int t = threadIdx.x;
    int v = (t < SCAN_BLOCKS) ? d_bsum[t] : 0;
    sh[t] = v; __syncthreads();
    #pragma unroll
    for (int o = 1; o < 128; o <<= 1) {
        int x = (t >= o) ? sh[t - o] : 0;
        __syncthreads();
        sh[t] += x;
        __syncthreads();
    }
    if (t < SCAN_BLOCKS) d_bsum[t] = sh[t] - v;  // exclusive
}

// scan stage C: per-element scan + base
__global__ void scanC_kernel() {
    __shared__ int sh[SCAN_CHUNK];
    int b = blockIdx.x, t = threadIdx.x;
    int idx = b * SCAN_CHUNK + t;
    int v = (idx < NN) ? d_cnt[idx] : 0;
    sh[t] = v; __syncthreads();
    for (int o = 1; o < SCAN_CHUNK; o <<= 1) {
        int x = (t >= o) ? sh[t - o] : 0;
        __syncthreads();
        sh[t] += x;
        __syncthreads();
    }
    int excl = sh[t] - v + d_bsum[b];
    if (idx < NN) { d_off[idx] = excl; d_cur[idx] = excl; }
    if (idx == NN - 1) d_off[NN] = excl + v;
}

// scatter + layer-1 attention weights (lin1's asrc/adst already computed)
__global__ void scatter_kernel(const int* __restrict__ ei, const float* __restrict__ ea,
                               const float* __restrict__ asrc, const float* __restrict__ adst) {
    int i = blockIdx.x * blockDim.x + threadIdx.x;
    if (i < EE) {
        int s  = ei[i];
        int dd = ei[EE + i];
        int pos = atomicAdd(&d_cur[dd], 1);
        d_csr_src[pos] = s;
        d_w[pos] = __expf(lrelu(asrc[s] + adst[dd] + ea[i] * d_cedge[0]));
        d_pos[i] = pos;
    }
}

// layer-2 attention weights, edge-parallel over the original edge list
__global__ void w2_kernel(const int* __restrict__ ei, const float* __restrict__ ea,
                          const float* __restrict__ asrc, const float* __restrict__ adst) {
    int i = blockIdx.x * blockDim.x + threadIdx.x;
    if (i < EE) {
        int s  = ei[i];
        int dd = ei[EE + i];
        d_w[d_pos[i]] = __expf(lrelu(asrc[s] + adst[dd] + ea[i] * d_cedge[1]));
    }
}

// ---------------- linear: xp = x @ W^T, plus asrc/adst projections ----------
#define LROWS 64
__global__ void __launch_bounds__(LROWS) lin_kernel(
    const float* __restrict__ x, const float* __restrict__ W,
    const float* __restrict__ a_src, const float* __restrict__ a_dst,
    float* __restrict__ xp, float* __restrict__ asrc, float* __restrict__ adst)
{
    __shared__ float Ws[FF * FF];
    __shared__ float As[FF], Ad[FF];
    __shared__ float Xs[LROWS][FF + 1];

    int tid = threadIdx.x;
    for (int i = tid; i < FF * FF; i += LROWS) Ws[i] = W[i];
    As[tid] = a_src[tid];
    Ad[tid] = a_dst[tid];

    int base = blockIdx.x * LROWS;
    for (int i = tid; i < LROWS * FF; i += LROWS) {
        int r = i / FF, c = i % FF;
        int node = base + r;
        Xs[r][c] = (node < NN) ? x[node * FF + c] : 0.f;
    }
    __syncthreads();

    float xr[FF];
    #pragma unroll
    for (int k = 0; k < FF; k++) xr[k] = Xs[tid][k];
    __syncthreads();

    int node = base + tid;
    float sa = 0.f, sd = 0.f;
    for (int j = 0; j < FF; j++) {
        float acc = 0.f;
        #pragma unroll
        for (int k = 0; k < FF; k++) acc += xr[k] * Ws[j * FF + k];
        Xs[tid][j] = acc;
        sa += acc * As[j];
        sd += acc * Ad[j];
    }
    if (node < NN) { asrc[node] = sa; adst[node] = sd; }
    __syncthreads();

    for (int i = tid; i < LROWS * FF; i += LROWS) {
        int r = i / FF, c = i % FF;
        int nd = base + r;
        if (nd < NN) xp[nd * FF + c] = Xs[r][c];
    }
}

// ---------------- aggregation: weights precomputed, pure gather -------------
__global__ void __launch_bounds__(256) agg_kernel(
    const float* __restrict__ xp, const float* __restrict__ asrc,
    const float* __restrict__ adst, const float* __restrict__ bias,
    float* __restrict__ hout, int cidx, int do_relu)
{
    int warp = (blockIdx.x * blockDim.x + threadIdx.x) >> 5;
    int lane = threadIdx.x & 31;
    if (warp >= NN) return;
    int d = warp;

    float ce = d_cedge[cidx];
    int start = d_off[d];
    int end   = d_off[d + 1];
    int c = end - start;
    float loop_ea = d_loop[d] / fmaxf((float)c, 1.f);
    float wself = __expf(lrelu(asrc[d] + adst[d] + loop_ea * ce));

    const float2* xp2 = (const float2*)xp;
    float2 xs = xp2[d * 32 + lane];
    float2 acc;
    acc.x = wself * xs.x;
    acc.y = wself * xs.y;
    float dsum = (lane == 0) ? wself : 0.f;

    for (int base = start; base < end; base += 32) {
        int j = base + lane;
        float w = 0.f;
        int s = 0;
        if (j < end) {
            s = d_csr_src[j];
            w = d_w[j];
        }
        dsum += w;
        int nn = min(32, end - base);
        #pragma unroll 8
        for (int jj = 0; jj < nn; jj++) {
            float wj = __shfl_sync(0xffffffff, w, jj);
            int   sj = __shfl_sync(0xffffffff, s, jj);
            float2 xv = xp2[sj * 32 + lane];
            acc.x += wj * xv.x;
            acc.y += wj * xv.y;
        }
    }
    #pragma unroll
    for (int o = 16; o > 0; o >>= 1)
        dsum += __shfl_xor_sync(0xffffffff, dsum, o);

    float inv = 1.f / dsum;
    float2 out;
    out.x = acc.x * inv + bias[2 * lane];
    out.y = acc.y * inv + bias[2 * lane + 1];
    if (do_relu) {
        out.x = fmaxf(out.x, 0.f);
        out.y = fmaxf(out.y, 0.f);
    }
    ((float2*)hout)[d * 32 + lane] = out;
}

// ---------------- pool + FC + log_softmax -----------------------------------
__device__ __forceinline__ int lowerb(const int* a, int n, int key) {
    int lo = 0, hi = n;
    while (lo < hi) {
        int mid = (lo + hi) >> 1;
        if (a[mid] < key) lo = mid + 1; else hi = mid;
    }
    return lo;
}

__global__ void __launch_bounds__(64) pool_kernel(
    const int* __restrict__ batch, const float* __restrict__ h,
    const float* __restrict__ fcW, const float* __restrict__ fcb,
    float* __restrict__ out)
{
    int g = blockIdx.x;
    int t = threadIdx.x;
    __shared__ int s_lo, s_hi;
    if (t == 0) s_lo = lowerb(batch, NN, g);
    if (t == 1) s_hi = lowerb(batch, NN, g + 1);
    __syncthreads();
    int lo = s_lo, hi = s_hi;

    float sum = 0.f;
    #pragma unroll 4
    for (int i = lo; i < hi; i++) sum += h[i * FF + t];
    float pooled = sum / fmaxf((float)(hi - lo), 1.f);

    __shared__ float P[FF];
    __shared__ float logits[OUTD];
    P[t] = pooled;
    __syncthreads();
    if (t < OUTD) {
        float acc = fcb[t];
        #pragma unroll
        for (int k = 0; k < FF; k++) acc += P[k] * fcW[t * FF + k];
        logits[t] = acc;
    }
    __syncthreads();
    if (t == 0) {
        float mx = -CUDART_INF_F;
        #pragma unroll
        for (int o = 0; o < OUTD; o++) mx = fmaxf(mx, logits[o]);
        float se = 0.f;
        #pragma unroll
        for (int o = 0; o < OUTD; o++) se += __expf(logits[o] - mx);
        float lse = mx + __logf(se);
        #pragma unroll
        for (int o = 0; o < OUTD; o++) out[g * OUTD + o] = logits[o] - lse;
    }
}

// ---------------- launch ----------------------------------------------------
extern "C" void kernel_launch(void* const* d_in, const int* in_sizes, int n_in,
                              void* d_out, int out_size) {
    const float* x    = (const float*)d_in[0];
    const int*   ei   = (const int*)  d_in[1];
    const float* ea   = (const float*)d_in[2];
    const int*   batch= (const int*)  d_in[3];
    const float* W1   = (const float*)d_in[4];
    const float* as1  = (const float*)d_in[5];
    const float* ad1  = (const float*)d_in[6];
    const float* We1  = (const float*)d_in[7];
    const float* ae1  = (const float*)d_in[8];
    const float* b1   = (const float*)d_in[9];
    const float* W2   = (const float*)d_in[10];
    const float* as2  = (const float*)d_in[11];
    const float* ad2  = (const float*)d_in[12];
    const float* We2  = (const float*)d_in[13];
    const float* ae2  = (const float*)d_in[14];
    const float* b2   = (const float*)d_in[15];
    const float* fcW  = (const float*)d_in[16];
    const float* fcb  = (const float*)d_in[17];
    float* out = (float*)d_out;
    (void)in_sizes; (void)n_in; (void)out_size;

    float* xp   = nullptr; cudaGetSymbolAddress((void**)&xp,   d_xp);
    float* h    = nullptr; cudaGetSymbolAddress((void**)&h,    d_h);
    float* asrc = nullptr; cudaGetSymbolAddress((void**)&asrc, d_asrc);
    float* adst = nullptr; cudaGetSymbolAddress((void**)&adst, d_adst);

    int agg_blocks = (NN * 32 + 255) / 256;

    zero_kernel<<<(NN + 255) / 256, 256>>>(We1, ae1, We2, ae2);
    count_kernel<<<(EE + 255) / 256, 256>>>(ei, ea);
    // lin1 before scatter: scatter folds layer-1 edge weights
    lin_kernel<<<(NN + LROWS - 1) / LROWS, LROWS>>>(x, W1, as1, ad1, xp, asrc, adst);
    scanA_kernel<<<SCAN_BLOCKS, 256>>>();
    scanB_kernel<<<1, 128>>>();
    scanC_kernel<<<SCAN_BLOCKS, SCAN_CHUNK>>>();
    scatter_kernel<<<(EE + 255) / 256, 256>>>(ei, ea, asrc, adst);

    // layer 1 aggregation (weights already in d_w)
    agg_kernel<<<agg_blocks, 256>>>(xp, asrc, adst, b1, h, 0, 1);
    // layer 2
    lin_kernel<<<(NN + LROWS - 1) / LROWS, LROWS>>>(h, W2, as2, ad2, xp, asrc, adst);
    w2_kernel<<<(EE + 255) / 256, 256>>>(ei, ea, asrc, adst);
    agg_kernel<<<agg_blocks, 256>>>(xp, asrc, adst, b2, h, 1, 0);
    // pool + fc + log_softmax
    pool_kernel<<<GG, FF>>>(batch, h, fcW, fcb, out);
}

// round 11
// speedup vs baseline: 1.1188x; 1.1188x over previous
#include <cuda_runtime.h>
#include <cuda_bf16.h>
#include <cuda_fp16.h>
#include <math_constants.h>

#define NN 100000
#define EE 800000
#define GG 512
#define FF 64
#define OUTD 10

#define SCAN_CHUNK 1024
#define SCAN_BLOCKS ((NN + SCAN_CHUNK - 1) / SCAN_CHUNK)

// ---------------- scratch (device globals; no allocation allowed) -----------
__device__ int     d_cnt[NN];
__device__ float   d_loop[NN];
__device__ int     d_off[NN + 1];
__device__ int     d_cur[NN];
__device__ int     d_bsum[SCAN_BLOCKS];
__device__ int     d_csr_src[EE];
__device__ float   d_csr_ea[EE];
__device__ __half2 d_xph[NN * (FF / 2)];   // fp16 features for the gather path
__device__ float   d_h[NN * FF];
__device__ float   d_asrc[NN];
__device__ float   d_adst[NN];
__device__ float   d_cedge[2];

__device__ __forceinline__ float lrelu(float x) {
    return fmaxf(x, 0.2f * x);
}

// ---------------- zero + cedge (fused; single-warp, NO barrier) --------------
__global__ void zero_kernel(const float* __restrict__ We1, const float* __restrict__ ae1,
                            const float* __restrict__ We2, const float* __restrict__ ae2) {
    int i = blockIdx.x * blockDim.x + threadIdx.x;
    if (i < NN) { d_cnt[i] = 0; d_loop[i] = 0.f; }
    if (blockIdx.x == 0 && threadIdx.x < 32) {
        int t = threadIdx.x;
        float p1 = We1[t] * ae1[t] + We1[t + 32] * ae1[t + 32];
        float p2 = We2[t] * ae2[t] + We2[t + 32] * ae2[t + 32];
        #pragma unroll
        for (int o = 16; o > 0; o >>= 1) {
            p1 += __shfl_xor_sync(0xffffffff, p1, o);
            p2 += __shfl_xor_sync(0xffffffff, p2, o);
        }
        if (t == 0) { d_cedge[0] = p1; d_cedge[1] = p2; }
    }
}

// ---------------- CSR construction ------------------------------------------
__global__ void count_kernel(const int* __restrict__ ei, const float* __restrict__ ea) {
    int i = blockIdx.x * blockDim.x + threadIdx.x;
    if (i < EE) {
        int dd = ei[EE + i];
        atomicAdd(&d_cnt[dd], 1);
        atomicAdd(&d_loop[dd], ea[i]);
    }
}

__global__ void scanA_kernel() {
    __shared__ int sh[256];
    int b = blockIdx.x, t = threadIdx.x;
    int s = 0;
    for (int i = t; i < SCAN_CHUNK; i += 256) {
        int idx = b * SCAN_CHUNK + i;
        if (idx < NN) s += d_cnt[idx];
    }
    sh[t] = s; __syncthreads();
    for (int o = 128; o > 0; o >>= 1) {
        if (t < o) sh[t] += sh[t + o];
        __syncthreads();
    }
    if (t == 0) d_bsum[b] = sh[0];
}

__global__ void scanB_kernel() {
    __shared__ int sh[128];
    int t = threadIdx.x;
    int v = (t < SCAN_BLOCKS) ? d_bsum[t] : 0;
    sh[t] = v; __syncthreads();
    #pragma unroll
    for (int o = 1; o < 128; o <<= 1) {
        int x = (t >= o) ? sh[t - o] : 0;
        __syncthreads();
        sh[t] += x;
        __syncthreads();
    }
    if (t < SCAN_BLOCKS) d_bsum[t] = sh[t] - v;  // exclusive
}

__global__ void scanC_kernel() {
    __shared__ int sh[SCAN_CHUNK];
    int b = blockIdx.x, t = threadIdx.x;
    int idx = b * SCAN_CHUNK + t;
    int v = (idx < NN) ? d_cnt[idx] : 0;
    sh[t] = v; __syncthreads();
    for (int o = 1; o < SCAN_CHUNK; o <<= 1) {
        int x = (t >= o) ? sh[t - o] : 0;
        __syncthreads();
        sh[t] += x;
        __syncthreads();
    }
    int excl = sh[t] - v + d_bsum[b];
    if (idx < NN) { d_off[idx] = excl; d_cur[idx] = excl; }
    if (idx == NN - 1) d_off[NN] = excl + v;
}

__global__ void scatter_kernel(const int* __restrict__ ei, const float* __restrict__ ea) {
    int i = blockIdx.x * blockDim.x + threadIdx.x;
    if (i < EE) {
        int dd = ei[EE + i];
        int pos = atomicAdd(&d_cur[dd], 1);
        d_csr_src[pos] = ei[i];
        d_csr_ea[pos] = ea[i];
    }
}

// ---------------- linear: xph = half(x @ W^T), plus asrc/adst ---------------
#define LROWS 64
__global__ void __launch_bounds__(LROWS) lin_kernel(
    const float* __restrict__ x, const float* __restrict__ W,
    const float* __restrict__ a_src, const float* __restrict__ a_dst,
    __half2* __restrict__ xph, float* __restrict__ asrc, float* __restrict__ adst)
{
    __shared__ float Ws[FF * FF];
    __shared__ float As[FF], Ad[FF];
    __shared__ float Xs[LROWS][FF + 1];

    int tid = threadIdx.x;
    for (int i = tid; i < FF * FF; i += LROWS) Ws[i] = W[i];
    As[tid] = a_src[tid];
    Ad[tid] = a_dst[tid];

    int base = blockIdx.x * LROWS;
    for (int i = tid; i < LROWS * FF; i += LROWS) {
        int r = i / FF, c = i % FF;
        int node = base + r;
        Xs[r][c] = (node < NN) ? x[node * FF + c] : 0.f;
    }
    __syncthreads();

    float xr[FF];
    #pragma unroll
    for (int k = 0; k < FF; k++) xr[k] = Xs[tid][k];
    __syncthreads();

    int node = base + tid;
    float sa = 0.f, sd = 0.f;
    for (int j = 0; j < FF; j++) {
        float acc = 0.f;
        #pragma unroll
        for (int k = 0; k < FF; k++) acc += xr[k] * Ws[j * FF + k];
        Xs[tid][j] = acc;
        sa += acc * As[j];
        sd += acc * Ad[j];
    }
    if (node < NN) { asrc[node] = sa; adst[node] = sd; }
    __syncthreads();

    // write fp16 feature rows (coalesced 4B stores)
    for (int i = tid; i < LROWS * (FF / 2); i += LROWS) {
        int r = i / (FF / 2), c2 = i % (FF / 2);
        int nd = base + r;
        if (nd < NN)
            xph[nd * (FF / 2) + c2] = __floats2half2_rn(Xs[r][2 * c2], Xs[r][2 * c2 + 1]);
    }
}

// ---------------- aggregation: single-pass softmax, fp16 feature gather -----
__global__ void __launch_bounds__(256) agg_kernel(
    const __half2* __restrict__ xph, const float* __restrict__ asrc,
    const float* __restrict__ adst, const float* __restrict__ bias,
    float* __restrict__ hout, int cidx, int do_relu)
{
    int warp = (blockIdx.x * blockDim.x + threadIdx.x) >> 5;
    int lane = threadIdx.x & 31;
    if (warp >= NN) return;
    int d = warp;

    float ce = d_cedge[cidx];
    int start = d_off[d];
    int end   = d_off[d + 1];
    float adst_d = adst[d];
    int c = end - start;
    float loop_ea = d_loop[d] / fmaxf((float)c, 1.f);
    float wself = __expf(lrelu(asrc[d] + adst_d + loop_ea * ce));

    float2 xs = __half22float2(xph[d * 32 + lane]);
    float2 acc;
    acc.x = wself * xs.x;
    acc.y = wself * xs.y;
    float dsum = (lane == 0) ? wself : 0.f;

    for (int base = start; base < end; base += 32) {
        int j = base + lane;
        float w = 0.f;
        int s = 0;
        if (j < end) {
            s = d_csr_src[j];
            w = __expf(lrelu(asrc[s] + adst_d + d_csr_ea[j] * ce));
        }
        dsum += w;
        int nn = min(32, end - base);
        #pragma unroll 4
        for (int jj = 0; jj < nn; jj++) {
            float wj = __shfl_sync(0xffffffff, w, jj);
            int   sj = __shfl_sync(0xffffffff, s, jj);
            float2 xv = __half22float2(xph[sj * 32 + lane]);
            acc.x += wj * xv.x;
            acc.y += wj * xv.y;
        }
    }
    #pragma unroll
    for (int o = 16; o > 0; o >>= 1)
        dsum += __shfl_xor_sync(0xffffffff, dsum, o);

    float inv = 1.f / dsum;
    float2 out;
    out.x = acc.x * inv + bias[2 * lane];
    out.y = acc.y * inv + bias[2 * lane + 1];
    if (do_relu) {
        out.x = fmaxf(out.x, 0.f);
        out.y = fmaxf(out.y, 0.f);
    }
    ((float2*)hout)[d * 32 + lane] = out;
}

// ---------------- pool + FC + log_softmax -----------------------------------
__device__ __forceinline__ int lowerb(const int* a, int n, int key) {
    int lo = 0, hi = n;
    while (lo < hi) {
        int mid = (lo + hi) >> 1;
        if (a[mid] < key) lo = mid + 1; else hi = mid;
    }
    return lo;
}

__global__ void __launch_bounds__(64) pool_kernel(
    const int* __restrict__ batch, const float* __restrict__ h,
    const float* __restrict__ fcW, const float* __restrict__ fcb,
    float* __restrict__ out)
{
    int g = blockIdx.x;
    int t = threadIdx.x;
    __shared__ int s_lo, s_hi;
    if (t == 0) s_lo = lowerb(batch, NN, g);
    if (t == 1) s_hi = lowerb(batch, NN, g + 1);
    __syncthreads();
    int lo = s_lo, hi = s_hi;

    float sum = 0.f;
    #pragma unroll 4
    for (int i = lo; i < hi; i++) sum += h[i * FF + t];
    float pooled = sum / fmaxf((float)(hi - lo), 1.f);

    __shared__ float P[FF];
    __shared__ float logits[OUTD];
    P[t] = pooled;
    __syncthreads();
    if (t < OUTD) {
        float acc = fcb[t];
        #pragma unroll
        for (int k = 0; k < FF; k++) acc += P[k] * fcW[t * FF + k];
        logits[t] = acc;
    }
    __syncthreads();
    if (t == 0) {
        float mx = -CUDART_INF_F;
        #pragma unroll
        for (int o = 0; o < OUTD; o++) mx = fmaxf(mx, logits[o]);
        float se = 0.f;
        #pragma unroll
        for (int o = 0; o < OUTD; o++) se += __expf(logits[o] - mx);
        float lse = mx + __logf(se);
        #pragma unroll
        for (int o = 0; o < OUTD; o++) out[g * OUTD + o] = logits[o] - lse;
    }
}

// ---------------- launch ----------------------------------------------------
extern "C" void kernel_launch(void* const* d_in, const int* in_sizes, int n_in,
                              void* d_out, int out_size) {
    const float* x    = (const float*)d_in[0];
    const int*   ei   = (const int*)  d_in[1];
    const float* ea   = (const float*)d_in[2];
    const int*   batch= (const int*)  d_in[3];
    const float* W1   = (const float*)d_in[4];
    const float* as1  = (const float*)d_in[5];
    const float* ad1  = (const float*)d_in[6];
    const float* We1  = (const float*)d_in[7];
    const float* ae1  = (const float*)d_in[8];
    const float* b1   = (const float*)d_in[9];
    const float* W2   = (const float*)d_in[10];
    const float* as2  = (const float*)d_in[11];
    const float* ad2  = (const float*)d_in[12];
    const float* We2  = (const float*)d_in[13];
    const float* ae2  = (const float*)d_in[14];
    const float* b2   = (const float*)d_in[15];
    const float* fcW  = (const float*)d_in[16];
    const float* fcb  = (const float*)d_in[17];
    float* out = (float*)d_out;
    (void)in_sizes; (void)n_in; (void)out_size;

    // CSR build
    zero_kernel<<<(NN + 255) / 256, 256>>>(We1, ae1, We2, ae2);
    count_kernel<<<(EE + 255) / 256, 256>>>(ei, ea);
    scanA_kernel<<<SCAN_BLOCKS, 256>>>();
    scanB_kernel<<<1, 128>>>();
    scanC_kernel<<<SCAN_BLOCKS, SCAN_CHUNK>>>();
    scatter_kernel<<<(EE + 255) / 256, 256>>>(ei, ea);

    __half2* xph = nullptr; cudaGetSymbolAddress((void**)&xph, d_xph);
    float* h     = nullptr; cudaGetSymbolAddress((void**)&h,    d_h);
    float* asrc  = nullptr; cudaGetSymbolAddress((void**)&asrc, d_asrc);
    float* adst  = nullptr; cudaGetSymbolAddress((void**)&adst, d_adst);

    int agg_blocks = (NN * 32 + 255) / 256;

    // layer 1
    lin_kernel<<<(NN + LROWS - 1) / LROWS, LROWS>>>(x, W1, as1, ad1, xph, asrc, adst);
    agg_kernel<<<agg_blocks, 256>>>(xph, asrc, adst, b1, h, 0, 1);
    // layer 2
    lin_kernel<<<(NN + LROWS - 1) / LROWS, LROWS>>>(h, W2, as2, ad2, xph, asrc, adst);
    agg_kernel<<<agg_blocks, 256>>>(xph, asrc, adst, b2, h, 1, 0);
    // pool + fc + log_softmax
    pool_kernel<<<GG, FF>>>(batch, h, fcW, fcb, out);
}